// round 3
// baseline (speedup 1.0000x reference)
#include <cuda_runtime.h>

// Problem constants (fixed by reference setup_inputs)
#define BROWS 16384
#define DCOLS 512
#define D4    (DCOLS / 4)          // 128 float4 per row
#define WARPS_PER_BLOCK 16
#define THREADS_PER_BLOCK (WARPS_PER_BLOCK * 32)
#define NBLOCKS (BROWS / WARPS_PER_BLOCK)   // 1024
#define INV_T 10.0f                 // 1 / TEMPERATURE

// Scratch for deterministic single-kernel reduction (no cudaMalloc allowed)
__device__ float g_partial[NBLOCKS];
__device__ unsigned int g_count;    // zero-initialized; last block resets it

__global__ __launch_bounds__(THREADS_PER_BLOCK)
void contrastive_fused_kernel(const float4* __restrict__ shared_i,
                              const float4* __restrict__ specific_i,
                              const float4* __restrict__ shared_j,
                              const float4* __restrict__ specific_j,
                              float* __restrict__ out) {
    const int warp = threadIdx.x >> 5;
    const int lane = threadIdx.x & 31;
    const int row  = blockIdx.x * WARPS_PER_BLOCK + warp;

    const size_t rowbase = (size_t)row * D4;

    float s_ss = 0.f, s_sp = 0.f, s_ps = 0.f, s_pp = 0.f;

    // 512 floats per row = 128 float4; 32 lanes -> 4 iterations.
    // Fully coalesced; __ldcs = streaming (read-once, evict-first).
    #pragma unroll
    for (int it = 0; it < D4 / 32; ++it) {
        const size_t idx = rowbase + it * 32 + lane;
        const float4 a = __ldcs(&shared_i[idx]);
        const float4 b = __ldcs(&specific_i[idx]);
        const float4 c = __ldcs(&shared_j[idx]);
        const float4 d = __ldcs(&specific_j[idx]);

        s_ss = fmaf(a.x, c.x, s_ss); s_ss = fmaf(a.y, c.y, s_ss);
        s_ss = fmaf(a.z, c.z, s_ss); s_ss = fmaf(a.w, c.w, s_ss);

        s_sp = fmaf(a.x, d.x, s_sp); s_sp = fmaf(a.y, d.y, s_sp);
        s_sp = fmaf(a.z, d.z, s_sp); s_sp = fmaf(a.w, d.w, s_sp);

        s_ps = fmaf(b.x, c.x, s_ps); s_ps = fmaf(b.y, c.y, s_ps);
        s_ps = fmaf(b.z, c.z, s_ps); s_ps = fmaf(b.w, c.w, s_ps);

        s_pp = fmaf(b.x, d.x, s_pp); s_pp = fmaf(b.y, d.y, s_pp);
        s_pp = fmaf(b.z, d.z, s_pp); s_pp = fmaf(b.w, d.w, s_pp);
    }

    // Warp-level reduction of the 4 dot products
    #pragma unroll
    for (int off = 16; off > 0; off >>= 1) {
        s_ss += __shfl_down_sync(0xffffffffu, s_ss, off);
        s_sp += __shfl_down_sync(0xffffffffu, s_sp, off);
        s_ps += __shfl_down_sync(0xffffffffu, s_ps, off);
        s_pp += __shfl_down_sync(0xffffffffu, s_pp, off);
    }

    __shared__ float sh_row[WARPS_PER_BLOCK];
    if (lane == 0) {
        const float l0 = s_ss * INV_T;
        const float l1 = s_sp * INV_T;
        const float l2 = s_ps * INV_T;
        const float l3 = s_pp * INV_T;
        const float m  = fmaxf(fmaxf(l0, l1), fmaxf(l2, l3));
        const float lse = m + logf(expf(l0 - m) + expf(l1 - m) +
                                   expf(l2 - m) + expf(l3 - m));
        // per-row loss contribution: -(log_softmax[0]) = lse - l0
        sh_row[warp] = lse - l0;
    }
    __syncthreads();

    __shared__ bool is_last;
    if (threadIdx.x == 0) {
        float s = 0.f;
        #pragma unroll
        for (int i = 0; i < WARPS_PER_BLOCK; ++i) s += sh_row[i];
        g_partial[blockIdx.x] = s;
        __threadfence();                        // make partial visible
        unsigned int t = atomicAdd(&g_count, 1u);
        is_last = (t == NBLOCKS - 1u);
    }
    __syncthreads();

    // Last block performs the deterministic final reduction:
    // fixed index order + shuffle tree -> bitwise-identical every run.
    if (is_last) {
        __threadfence();                        // acquire all partials
        const int tid = threadIdx.x;
        // NBLOCKS = 1024, THREADS_PER_BLOCK = 512 -> 2 entries per thread
        float v = g_partial[tid] + g_partial[tid + THREADS_PER_BLOCK];

        #pragma unroll
        for (int off = 16; off > 0; off >>= 1)
            v += __shfl_down_sync(0xffffffffu, v, off);

        __shared__ float sh[WARPS_PER_BLOCK];
        if (lane == 0) sh[warp] = v;
        __syncthreads();

        if (warp == 0) {
            float w = (lane < WARPS_PER_BLOCK) ? sh[lane] : 0.f;
            #pragma unroll
            for (int off = 8; off > 0; off >>= 1)
                w += __shfl_down_sync(0xffffffffu, w, off);
            if (lane == 0) {
                out[0] = w / (float)BROWS;
                g_count = 0;                    // reset for next graph replay
            }
        }
    }
}

extern "C" void kernel_launch(void* const* d_in, const int* in_sizes, int n_in,
                              void* d_out, int out_size) {
    const float4* shared_i   = (const float4*)d_in[0];
    const float4* specific_i = (const float4*)d_in[1];
    const float4* shared_j   = (const float4*)d_in[2];
    const float4* specific_j = (const float4*)d_in[3];
    float* out = (float*)d_out;

    contrastive_fused_kernel<<<NBLOCKS, THREADS_PER_BLOCK>>>(
        shared_i, specific_i, shared_j, specific_j, out);
}

// round 4
// speedup vs baseline: 1.0726x; 1.0726x over previous
#include <cuda_runtime.h>

// Problem constants (fixed by reference setup_inputs)
#define BROWS 16384
#define DCOLS 512
#define D4    (DCOLS / 4)          // 128 float4 per row
#define WARPS_PER_BLOCK 8
#define THREADS_PER_BLOCK (WARPS_PER_BLOCK * 32)     // 256
#define NBLOCKS (BROWS / WARPS_PER_BLOCK)            // 2048
#define INV_T 10.0f                 // 1 / TEMPERATURE

// Scratch for deterministic single-kernel reduction (no cudaMalloc allowed)
__device__ float g_partial[NBLOCKS];
__device__ unsigned int g_count;    // zero-initialized; last block resets it

__global__ __launch_bounds__(THREADS_PER_BLOCK)
void contrastive_fused_kernel(const float4* __restrict__ shared_i,
                              const float4* __restrict__ specific_i,
                              const float4* __restrict__ shared_j,
                              const float4* __restrict__ specific_j,
                              float* __restrict__ out) {
    const int warp = threadIdx.x >> 5;
    const int lane = threadIdx.x & 31;
    const int row  = blockIdx.x * WARPS_PER_BLOCK + warp;

    const size_t rowbase = (size_t)row * D4;

    float s_ss = 0.f, s_sp = 0.f, s_ps = 0.f, s_pp = 0.f;

    // 512 floats per row = 128 float4; 32 lanes -> 4 iterations.
    // Fully coalesced; __ldg (RO-cache path) — measured faster than __ldcs.
    #pragma unroll
    for (int it = 0; it < D4 / 32; ++it) {
        const size_t idx = rowbase + it * 32 + lane;
        const float4 a = __ldg(&shared_i[idx]);
        const float4 b = __ldg(&specific_i[idx]);
        const float4 c = __ldg(&shared_j[idx]);
        const float4 d = __ldg(&specific_j[idx]);

        s_ss = fmaf(a.x, c.x, s_ss); s_ss = fmaf(a.y, c.y, s_ss);
        s_ss = fmaf(a.z, c.z, s_ss); s_ss = fmaf(a.w, c.w, s_ss);

        s_sp = fmaf(a.x, d.x, s_sp); s_sp = fmaf(a.y, d.y, s_sp);
        s_sp = fmaf(a.z, d.z, s_sp); s_sp = fmaf(a.w, d.w, s_sp);

        s_ps = fmaf(b.x, c.x, s_ps); s_ps = fmaf(b.y, c.y, s_ps);
        s_ps = fmaf(b.z, c.z, s_ps); s_ps = fmaf(b.w, c.w, s_ps);

        s_pp = fmaf(b.x, d.x, s_pp); s_pp = fmaf(b.y, d.y, s_pp);
        s_pp = fmaf(b.z, d.z, s_pp); s_pp = fmaf(b.w, d.w, s_pp);
    }

    // Warp-level reduction of the 4 dot products
    #pragma unroll
    for (int off = 16; off > 0; off >>= 1) {
        s_ss += __shfl_down_sync(0xffffffffu, s_ss, off);
        s_sp += __shfl_down_sync(0xffffffffu, s_sp, off);
        s_ps += __shfl_down_sync(0xffffffffu, s_ps, off);
        s_pp += __shfl_down_sync(0xffffffffu, s_pp, off);
    }

    __shared__ float sh_row[WARPS_PER_BLOCK];
    if (lane == 0) {
        const float l0 = s_ss * INV_T;
        const float l1 = s_sp * INV_T;
        const float l2 = s_ps * INV_T;
        const float l3 = s_pp * INV_T;
        const float m  = fmaxf(fmaxf(l0, l1), fmaxf(l2, l3));
        const float lse = m + logf(expf(l0 - m) + expf(l1 - m) +
                                   expf(l2 - m) + expf(l3 - m));
        // per-row loss contribution: -(log_softmax[0]) = lse - l0
        sh_row[warp] = lse - l0;
    }
    __syncthreads();

    __shared__ bool is_last;
    if (threadIdx.x == 0) {
        float s = 0.f;
        #pragma unroll
        for (int i = 0; i < WARPS_PER_BLOCK; ++i) s += sh_row[i];
        g_partial[blockIdx.x] = s;
        __threadfence();                        // make partial visible
        unsigned int t = atomicAdd(&g_count, 1u);
        is_last = (t == NBLOCKS - 1u);
    }
    __syncthreads();

    // Last block performs the deterministic final reduction:
    // fixed index order + shuffle tree -> bitwise-identical every run.
    if (is_last) {
        __threadfence();                        // acquire all partials
        const int tid = threadIdx.x;
        // NBLOCKS = 2048, THREADS_PER_BLOCK = 256 -> 8 entries per thread
        float v = 0.f;
        #pragma unroll
        for (int k = 0; k < NBLOCKS / THREADS_PER_BLOCK; ++k)
            v += g_partial[tid + k * THREADS_PER_BLOCK];

        #pragma unroll
        for (int off = 16; off > 0; off >>= 1)
            v += __shfl_down_sync(0xffffffffu, v, off);

        __shared__ float sh[WARPS_PER_BLOCK];
        if (lane == 0) sh[warp] = v;
        __syncthreads();

        if (warp == 0) {
            float w = (lane < WARPS_PER_BLOCK) ? sh[lane] : 0.f;
            #pragma unroll
            for (int off = WARPS_PER_BLOCK / 2; off > 0; off >>= 1)
                w += __shfl_down_sync(0xffffffffu, w, off);
            if (lane == 0) {
                out[0] = w / (float)BROWS;
                g_count = 0;                    // reset for next graph replay
            }
        }
    }
}

extern "C" void kernel_launch(void* const* d_in, const int* in_sizes, int n_in,
                              void* d_out, int out_size) {
    const float4* shared_i   = (const float4*)d_in[0];
    const float4* specific_i = (const float4*)d_in[1];
    const float4* shared_j   = (const float4*)d_in[2];
    const float4* specific_j = (const float4*)d_in[3];
    float* out = (float*)d_out;

    contrastive_fused_kernel<<<NBLOCKS, THREADS_PER_BLOCK>>>(
        shared_i, specific_i, shared_j, specific_j, out);
}